// round 4
// baseline (speedup 1.0000x reference)
#include <cuda_runtime.h>
#include <cuda_fp16.h>
#include <math.h>

// ---------------------------------------------------------------------------
// GAT graph encoder, 2 layers. CSR-by-dst per call; softmax max cancels.
// h features stored fp16 (half2) to halve the edge-gather L2 traffic; all
// accumulation + attention logits fp32.
// ---------------------------------------------------------------------------

#define NMAX 100000
#define EMAX 1600000
#define NEG_SLOPE 0.2f
#define SCAN_CHUNK 4096

__device__ __half2 g_h1h[NMAX * 64];    // layer1 features, fp16 pairs
__device__ __half2 g_h2h[NMAX * 64];    // layer2 features, fp16 pairs
__device__ float   g_act1[NMAX * 128];  // layer1 activations (GEMM2 input), fp32
__device__ float   g_asrc1[NMAX * 4];
__device__ float   g_adst1[NMAX * 4];
__device__ float   g_asrc2[NMAX];
__device__ float   g_adst2[NMAX];
__device__ int     g_cnt[NMAX];
__device__ int     g_off[NMAX + 1];
__device__ int     g_pos[NMAX];
__device__ int     g_srcs[EMAX];
__device__ int     g_bsum[64];
__device__ int     g_bpre[64];
__device__ int     g_is64;

// --------------------------- edge dtype sniffing ---------------------------
__global__ void detect_kernel(const void* a, int n_nodes) {
    if (blockIdx.x == 0 && threadIdx.x == 0) {
        const unsigned long long* p = (const unsigned long long*)a;
        int is64 = 1;
        for (int i = 0; i < 256; i++) {
            if (p[i] >= (unsigned long long)n_nodes) { is64 = 0; break; }
        }
        g_is64 = is64;
    }
}

__device__ __forceinline__ int edge_val(const void* a, long long idx) {
    if (g_is64) return (int)((const long long*)a)[idx];
    return ((const int*)a)[idx];
}

// ------------------------------- CSR build ---------------------------------
__global__ void zero_cnt_kernel(int n) {
    int i = blockIdx.x * blockDim.x + threadIdx.x;
    if (i < n) g_cnt[i] = 0;
}

__global__ void hist_kernel(const void* a, int E) {
    int e = blockIdx.x * blockDim.x + threadIdx.x;
    if (e >= E) return;
    int dst = edge_val(a, (long long)E + e);
    atomicAdd(&g_cnt[dst], 1);
}

__global__ void scanA_kernel(int n) {
    __shared__ int wsum[32];
    int b = blockIdx.x, tid = threadIdx.x;
    int lane = tid & 31, warp = tid >> 5;
    int base = b * SCAN_CHUNK + tid * 4;
    int v0 = 0, v1 = 0, v2 = 0, v3 = 0;
    if (base + 3 < n) {
        int4 v = *(const int4*)&g_cnt[base];
        v0 = v.x; v1 = v.y; v2 = v.z; v3 = v.w;
    } else if (base < n) {
        v0 = g_cnt[base];
        if (base + 1 < n) v1 = g_cnt[base + 1];
        if (base + 2 < n) v2 = g_cnt[base + 2];
    }
    int tsum = v0 + v1 + v2 + v3;
    int x = tsum;
    #pragma unroll
    for (int d = 1; d < 32; d <<= 1) {
        int t = __shfl_up_sync(0xffffffffu, x, d);
        if (lane >= d) x += t;
    }
    if (lane == 31) wsum[warp] = x;
    __syncthreads();
    if (warp == 0) {
        int y = wsum[lane];
        #pragma unroll
        for (int d = 1; d < 32; d <<= 1) {
            int t = __shfl_up_sync(0xffffffffu, y, d);
            if (lane >= d) y += t;
        }
        wsum[lane] = y;
    }
    __syncthreads();
    int excl = (warp ? wsum[warp - 1] : 0) + (x - tsum);
    if (base < n) {
        g_off[base] = excl;
        if (base + 1 < n) g_off[base + 1] = excl + v0;
        if (base + 2 < n) g_off[base + 2] = excl + v0 + v1;
        if (base + 3 < n) g_off[base + 3] = excl + v0 + v1 + v2;
    }
    if (tid == 0) g_bsum[b] = wsum[31];
}

__global__ void scanB_kernel(int nblocks, int n) {
    int lane = threadIdx.x;
    int v = (lane < nblocks) ? g_bsum[lane] : 0;
    int x = v;
    #pragma unroll
    for (int d = 1; d < 32; d <<= 1) {
        int t = __shfl_up_sync(0xffffffffu, x, d);
        if (lane >= d) x += t;
    }
    if (lane < nblocks) g_bpre[lane] = x - v;
    if (lane == 31) g_off[n] = x;
}

__global__ void scanC_kernel(int n) {
    int i = blockIdx.x * blockDim.x + threadIdx.x;
    if (i < n) {
        int o = g_off[i] + g_bpre[i >> 12];
        g_off[i] = o;
        g_pos[i] = o;
    }
}

__global__ void scatter_kernel(const void* a, int E) {
    int e = blockIdx.x * blockDim.x + threadIdx.x;
    if (e >= E) return;
    int src = edge_val(a, e);
    int dst = edge_val(a, (long long)E + e);
    int p = atomicAdd(&g_pos[dst], 1);
    g_srcs[p] = src;
}

// --------------------- GEMM + attention-logit epilogue ---------------------
// C[M,128] = A[M,128] @ W[128,128] fp32 accum; writes h as half2 and the
// per-node attention logits (asrc/adst) from the fp32 accumulators.
// Double-buffered smem. HEADS = 4 (layer1) or 1 (layer2).
template <int HEADS>
__global__ void gemm_att_kernel(const float* __restrict__ A,
                                const float* __restrict__ W,
                                const float* __restrict__ att_src,
                                const float* __restrict__ att_dst, int M) {
    __shared__ float As[2][16][132];
    __shared__ float Ws[2][16][128];
    int t = threadIdx.x;
    int tx = t & 15;
    int ty = t >> 4;
    int row0 = blockIdx.x * 128;
    float acc[8][8];
    #pragma unroll
    for (int m = 0; m < 8; m++)
        #pragma unroll
        for (int n = 0; n < 8; n++) acc[m][n] = 0.f;

    float4 ra[2], rw[2];
    int ar[2], ac4[2], wr[2], wc4[2];
    #pragma unroll
    for (int i = 0; i < 2; i++) {
        int idx = t + i * 256;
        ar[i] = idx >> 2; ac4[i] = idx & 3;
        wr[i] = idx >> 5; wc4[i] = idx & 31;
    }

    // prologue: load tile 0 into buffer 0
    #pragma unroll
    for (int i = 0; i < 2; i++) {
        float4 v = make_float4(0.f, 0.f, 0.f, 0.f);
        if (row0 + ar[i] < M)
            v = *(const float4*)&A[(long long)(row0 + ar[i]) * 128 + ac4[i] * 4];
        As[0][ac4[i] * 4 + 0][ar[i]] = v.x;
        As[0][ac4[i] * 4 + 1][ar[i]] = v.y;
        As[0][ac4[i] * 4 + 2][ar[i]] = v.z;
        As[0][ac4[i] * 4 + 3][ar[i]] = v.w;
        *(float4*)&Ws[0][wr[i]][wc4[i] * 4] = *(const float4*)&W[wr[i] * 128 + wc4[i] * 4];
    }
    __syncthreads();

    #pragma unroll
    for (int kt = 0; kt < 8; kt++) {
        int cur = kt & 1, nxt = cur ^ 1;
        if (kt < 7) {
            #pragma unroll
            for (int i = 0; i < 2; i++) {
                ra[i] = make_float4(0.f, 0.f, 0.f, 0.f);
                if (row0 + ar[i] < M)
                    ra[i] = *(const float4*)&A[(long long)(row0 + ar[i]) * 128 + (kt + 1) * 16 + ac4[i] * 4];
                rw[i] = *(const float4*)&W[((kt + 1) * 16 + wr[i]) * 128 + wc4[i] * 4];
            }
        }
        #pragma unroll
        for (int k = 0; k < 16; k++) {
            float areg[8], breg[8];
            #pragma unroll
            for (int m = 0; m < 8; m++) areg[m] = As[cur][k][ty * 8 + m];
            #pragma unroll
            for (int n = 0; n < 8; n++) breg[n] = Ws[cur][k][tx * 8 + n];
            #pragma unroll
            for (int m = 0; m < 8; m++)
                #pragma unroll
                for (int n = 0; n < 8; n++) acc[m][n] += areg[m] * breg[n];
        }
        if (kt < 7) {
            #pragma unroll
            for (int i = 0; i < 2; i++) {
                As[nxt][ac4[i] * 4 + 0][ar[i]] = ra[i].x;
                As[nxt][ac4[i] * 4 + 1][ar[i]] = ra[i].y;
                As[nxt][ac4[i] * 4 + 2][ar[i]] = ra[i].z;
                As[nxt][ac4[i] * 4 + 3][ar[i]] = ra[i].w;
                *(float4*)&Ws[nxt][wr[i]][wc4[i] * 4] = rw[i];
            }
            __syncthreads();
        }
    }

    // epilogue: write h (half2) + attention logits from fp32 accumulators
    float avs[8], avd[8];
    #pragma unroll
    for (int n = 0; n < 8; n++) {
        avs[n] = att_src[tx * 8 + n];
        avd[n] = att_dst[tx * 8 + n];
    }
    __half2* H = (HEADS == 4) ? g_h1h : g_h2h;

    #pragma unroll
    for (int m = 0; m < 8; m++) {
        int r = row0 + ty * 8 + m;
        float ps = 0.f, pd = 0.f;
        #pragma unroll
        for (int n = 0; n < 8; n++) {
            ps += acc[m][n] * avs[n];
            pd += acc[m][n] * avd[n];
        }
        if (HEADS == 4) {
            // reduce within 4-lane tx-groups (one head each, cols tx*8..)
            #pragma unroll
            for (int off = 1; off <= 2; off <<= 1) {
                ps += __shfl_xor_sync(0xffffffffu, ps, off);
                pd += __shfl_xor_sync(0xffffffffu, pd, off);
            }
            if ((tx & 3) == 0 && r < M) {
                g_asrc1[r * 4 + (tx >> 2)] = ps;
                g_adst1[r * 4 + (tx >> 2)] = pd;
            }
        } else {
            #pragma unroll
            for (int off = 1; off <= 8; off <<= 1) {
                ps += __shfl_xor_sync(0xffffffffu, ps, off);
                pd += __shfl_xor_sync(0xffffffffu, pd, off);
            }
            if (tx == 0 && r < M) {
                g_asrc2[r] = ps;
                g_adst2[r] = pd;
            }
        }
        if (r < M) {
            __half2 hh[4];
            #pragma unroll
            for (int q = 0; q < 4; q++)
                hh[q] = __floats2half2_rn(acc[m][2 * q], acc[m][2 * q + 1]);
            *(uint4*)&H[(long long)r * 64 + tx * 4] = *(uint4*)hh;
        }
    }
}

// ------------------- fused edge softmax + aggregation ----------------------
__device__ __forceinline__ float leaky_exp(float l) {
    l = l > 0.f ? l : NEG_SLOPE * l;
    return __expf(l);
}
__device__ __forceinline__ float elu(float v) {
    return v > 0.f ? v : expm1f(v);
}

// Layer 1: warp per dst node; h gathered as half2 (256B/row).
// Lane covers channels {2l,2l+1} (half2 l) and {64+2l,64+2l+1} (half2 32+l).
__global__ void agg1_kernel(int N, const float* __restrict__ b1) {
    int node = (blockIdx.x * blockDim.x + threadIdx.x) >> 5;
    int lane = threadIdx.x & 31;
    if (node >= N) return;
    int beg = g_off[node], end = g_off[node + 1];
    float4 ad = *(const float4*)&g_adst1[node * 4];
    float2 accL = make_float2(0.f, 0.f), accH = make_float2(0.f, 0.f);
    float s0 = 0.f, s1 = 0.f, s2 = 0.f, s3 = 0.f;
    bool lo = lane < 16;
    for (int base = beg; base < end; base += 32) {
        int e = base + lane;
        int src = 0;
        float w0 = 0.f, w1 = 0.f, w2 = 0.f, w3 = 0.f;
        if (e < end) {
            src = g_srcs[e];
            float4 as = *(const float4*)&g_asrc1[src * 4];
            w0 = leaky_exp(as.x + ad.x);
            w1 = leaky_exp(as.y + ad.y);
            w2 = leaky_exp(as.z + ad.z);
            w3 = leaky_exp(as.w + ad.w);
            s0 += w0; s1 += w1; s2 += w2; s3 += w3;
        }
        int cnt = min(32, end - base);
        #pragma unroll 4
        for (int j = 0; j < cnt; j++) {
            int   sj = __shfl_sync(0xffffffffu, src, j);
            float u0 = __shfl_sync(0xffffffffu, w0, j);
            float u1 = __shfl_sync(0xffffffffu, w1, j);
            float u2 = __shfl_sync(0xffffffffu, w2, j);
            float u3 = __shfl_sync(0xffffffffu, w3, j);
            const __half2* hp = &g_h1h[(long long)sj * 64];
            float2 fL = __half22float2(hp[lane]);
            float2 fH = __half22float2(hp[32 + lane]);
            float uL = lo ? u0 : u1;
            float uH = lo ? u2 : u3;
            accL.x += uL * fL.x; accL.y += uL * fL.y;
            accH.x += uH * fH.x; accH.y += uH * fH.y;
        }
    }
    #pragma unroll
    for (int off = 16; off; off >>= 1) {
        s0 += __shfl_xor_sync(0xffffffffu, s0, off);
        s1 += __shfl_xor_sync(0xffffffffu, s1, off);
        s2 += __shfl_xor_sync(0xffffffffu, s2, off);
        s3 += __shfl_xor_sync(0xffffffffu, s3, off);
    }
    float sL = (lo ? s0 : s1) + 1e-16f;
    float sH = (lo ? s2 : s3) + 1e-16f;
    float* op = &g_act1[(long long)node * 128];
    float2 o;
    o.x = elu(accL.x / sL + b1[2 * lane]);
    o.y = elu(accL.y / sL + b1[2 * lane + 1]);
    *(float2*)&op[2 * lane] = o;
    o.x = elu(accH.x / sH + b1[64 + 2 * lane]);
    o.y = elu(accH.y / sH + b1[64 + 2 * lane + 1]);
    *(float2*)&op[64 + 2 * lane] = o;
}

// Layer 2: single head. -> d_out (fp32)
__global__ void agg2_kernel(int N, const float* __restrict__ b2,
                            float* __restrict__ out) {
    int node = (blockIdx.x * blockDim.x + threadIdx.x) >> 5;
    int lane = threadIdx.x & 31;
    if (node >= N) return;
    int beg = g_off[node], end = g_off[node + 1];
    float ad = g_adst2[node];
    float2 accL = make_float2(0.f, 0.f), accH = make_float2(0.f, 0.f);
    float s = 0.f;
    for (int base = beg; base < end; base += 32) {
        int e = base + lane;
        int src = 0;
        float w = 0.f;
        if (e < end) {
            src = g_srcs[e];
            w = leaky_exp(g_asrc2[src] + ad);
            s += w;
        }
        int cnt = min(32, end - base);
        #pragma unroll 4
        for (int j = 0; j < cnt; j++) {
            int   sj = __shfl_sync(0xffffffffu, src, j);
            float u  = __shfl_sync(0xffffffffu, w, j);
            const __half2* hp = &g_h2h[(long long)sj * 64];
            float2 fL = __half22float2(hp[lane]);
            float2 fH = __half22float2(hp[32 + lane]);
            accL.x += u * fL.x; accL.y += u * fL.y;
            accH.x += u * fH.x; accH.y += u * fH.y;
        }
    }
    #pragma unroll
    for (int off = 16; off; off >>= 1)
        s += __shfl_xor_sync(0xffffffffu, s, off);
    float inv = 1.f / (s + 1e-16f);
    float* op = &out[(long long)node * 128];
    float2 o;
    o.x = elu(accL.x * inv + b2[2 * lane]);
    o.y = elu(accL.y * inv + b2[2 * lane + 1]);
    *(float2*)&op[2 * lane] = o;
    o.x = elu(accH.x * inv + b2[64 + 2 * lane]);
    o.y = elu(accH.y * inv + b2[64 + 2 * lane + 1]);
    *(float2*)&op[64 + 2 * lane] = o;
}

// ------------------------------- launch ------------------------------------
extern "C" void kernel_launch(void* const* d_in, const int* in_sizes, int n_in,
                              void* d_out, int out_size) {
    const float* x        = (const float*)d_in[0];
    const void*  a        = d_in[1];
    const float* W1       = (const float*)d_in[2];
    const float* att_src1 = (const float*)d_in[3];
    const float* att_dst1 = (const float*)d_in[4];
    const float* b1       = (const float*)d_in[5];
    const float* W2       = (const float*)d_in[6];
    const float* att_src2 = (const float*)d_in[7];
    const float* att_dst2 = (const float*)d_in[8];
    const float* b2       = (const float*)d_in[9];
    float* out = (float*)d_out;

    void* p_act1 = 0;
    cudaGetSymbolAddress(&p_act1, g_act1);
    float* act1 = (float*)p_act1;

    int N = in_sizes[0] / 128;
    int E = in_sizes[1] / 2;

    int eg = (E + 255) / 256;
    int ng = (N + 255) / 256;
    int wg = (N + 7) / 8;
    int gg = (N + 127) / 128;
    int sb = (N + SCAN_CHUNK - 1) / SCAN_CHUNK;

    detect_kernel<<<1, 32>>>(a, N);
    zero_cnt_kernel<<<ng, 256>>>(N);
    hist_kernel<<<eg, 256>>>(a, E);
    scanA_kernel<<<sb, 1024>>>(N);
    scanB_kernel<<<1, 32>>>(sb, N);
    scanC_kernel<<<ng, 256>>>(N);
    scatter_kernel<<<eg, 256>>>(a, E);

    // Layer 1
    gemm_att_kernel<4><<<gg, 256>>>(x, W1, att_src1, att_dst1, N);
    agg1_kernel<<<wg, 256>>>(N, b1);

    // Layer 2
    gemm_att_kernel<1><<<gg, 256>>>(act1, W2, att_src2, att_dst2, N);
    agg2_kernel<<<wg, 256>>>(N, b2, out);
}

// round 5
// speedup vs baseline: 1.1971x; 1.1971x over previous
#include <cuda_runtime.h>
#include <math.h>

// ---------------------------------------------------------------------------
// GAT graph encoder, 2 layers. CSR-by-dst per call; softmax max cancels.
// R3 structure + packed f32x2 GEMM + attention logits fused into GEMM epilogue.
// ---------------------------------------------------------------------------

#define NMAX 100000
#define EMAX 1600000
#define NEG_SLOPE 0.2f
#define SCAN_CHUNK 4096

typedef unsigned long long ull;

__device__ float g_h1[NMAX * 128];
__device__ float g_act1[NMAX * 128];
__device__ float g_h2[NMAX * 128];
__device__ float g_asrc1[NMAX * 4];
__device__ float g_adst1[NMAX * 4];
__device__ float g_asrc2[NMAX];
__device__ float g_adst2[NMAX];
__device__ int   g_cnt[NMAX];
__device__ int   g_off[NMAX + 1];
__device__ int   g_pos[NMAX];
__device__ int   g_srcs[EMAX];
__device__ int   g_bsum[64];
__device__ int   g_bpre[64];
__device__ int   g_is64;

// ------------------------- packed fp32 helpers -----------------------------
__device__ __forceinline__ ull f32x2_bcast(float a) {
    ull d;
    asm("mov.b64 %0, {%1, %1};" : "=l"(d) : "f"(a));
    return d;
}
__device__ __forceinline__ ull f32x2_fma(ull a, ull b, ull c) {
    ull d;
    asm("fma.rn.f32x2 %0, %1, %2, %3;" : "=l"(d) : "l"(a), "l"(b), "l"(c));
    return d;
}
__device__ __forceinline__ float2 f32x2_unpack(ull p) {
    float2 r;
    asm("mov.b64 {%0, %1}, %2;" : "=f"(r.x), "=f"(r.y) : "l"(p));
    return r;
}

// --------------------------- edge dtype sniffing ---------------------------
__global__ void detect_kernel(const void* a, int n_nodes) {
    if (blockIdx.x == 0 && threadIdx.x == 0) {
        const unsigned long long* p = (const unsigned long long*)a;
        int is64 = 1;
        for (int i = 0; i < 256; i++) {
            if (p[i] >= (unsigned long long)n_nodes) { is64 = 0; break; }
        }
        g_is64 = is64;
    }
}

__device__ __forceinline__ int edge_val(const void* a, long long idx) {
    if (g_is64) return (int)((const long long*)a)[idx];
    return ((const int*)a)[idx];
}

// ------------------------------- CSR build ---------------------------------
__global__ void zero_cnt_kernel(int n) {
    int i = blockIdx.x * blockDim.x + threadIdx.x;
    if (i < n) g_cnt[i] = 0;
}

__global__ void hist_kernel(const void* a, int E) {
    int e = blockIdx.x * blockDim.x + threadIdx.x;
    if (e >= E) return;
    int dst = edge_val(a, (long long)E + e);
    atomicAdd(&g_cnt[dst], 1);
}

__global__ void scanA_kernel(int n) {
    __shared__ int wsum[32];
    int b = blockIdx.x, tid = threadIdx.x;
    int lane = tid & 31, warp = tid >> 5;
    int base = b * SCAN_CHUNK + tid * 4;
    int v0 = 0, v1 = 0, v2 = 0, v3 = 0;
    if (base + 3 < n) {
        int4 v = *(const int4*)&g_cnt[base];
        v0 = v.x; v1 = v.y; v2 = v.z; v3 = v.w;
    } else if (base < n) {
        v0 = g_cnt[base];
        if (base + 1 < n) v1 = g_cnt[base + 1];
        if (base + 2 < n) v2 = g_cnt[base + 2];
    }
    int tsum = v0 + v1 + v2 + v3;
    int x = tsum;
    #pragma unroll
    for (int d = 1; d < 32; d <<= 1) {
        int t = __shfl_up_sync(0xffffffffu, x, d);
        if (lane >= d) x += t;
    }
    if (lane == 31) wsum[warp] = x;
    __syncthreads();
    if (warp == 0) {
        int y = wsum[lane];
        #pragma unroll
        for (int d = 1; d < 32; d <<= 1) {
            int t = __shfl_up_sync(0xffffffffu, y, d);
            if (lane >= d) y += t;
        }
        wsum[lane] = y;
    }
    __syncthreads();
    int excl = (warp ? wsum[warp - 1] : 0) + (x - tsum);
    if (base < n) {
        g_off[base] = excl;
        if (base + 1 < n) g_off[base + 1] = excl + v0;
        if (base + 2 < n) g_off[base + 2] = excl + v0 + v1;
        if (base + 3 < n) g_off[base + 3] = excl + v0 + v1 + v2;
    }
    if (tid == 0) g_bsum[b] = wsum[31];
}

__global__ void scanB_kernel(int nblocks, int n) {
    int lane = threadIdx.x;
    int v = (lane < nblocks) ? g_bsum[lane] : 0;
    int x = v;
    #pragma unroll
    for (int d = 1; d < 32; d <<= 1) {
        int t = __shfl_up_sync(0xffffffffu, x, d);
        if (lane >= d) x += t;
    }
    if (lane < nblocks) g_bpre[lane] = x - v;
    if (lane == 31) g_off[n] = x;
}

__global__ void scanC_kernel(int n) {
    int i = blockIdx.x * blockDim.x + threadIdx.x;
    if (i < n) {
        int o = g_off[i] + g_bpre[i >> 12];
        g_off[i] = o;
        g_pos[i] = o;
    }
}

__global__ void scatter_kernel(const void* a, int E) {
    int e = blockIdx.x * blockDim.x + threadIdx.x;
    if (e >= E) return;
    int src = edge_val(a, e);
    int dst = edge_val(a, (long long)E + e);
    int p = atomicAdd(&g_pos[dst], 1);
    g_srcs[p] = src;
}

// --------------------- GEMM (f32x2) + attention epilogue -------------------
// C[M,128] = A[M,128] @ W[128,128], fp32 via packed fma.rn.f32x2.
// Writes h (fp32) and per-node attention logits. HEADS = 4 or 1.
template <int HEADS>
__global__ void gemm_att_kernel(const float* __restrict__ A,
                                const float* __restrict__ W,
                                const float* __restrict__ att_src,
                                const float* __restrict__ att_dst,
                                float* __restrict__ H, int M) {
    __shared__ float As[16][132];   // transposed A tile
    __shared__ float Ws[16][128];
    int t = threadIdx.x;
    int tx = t & 15;
    int ty = t >> 4;
    int row0 = blockIdx.x * 128;
    ull acc2[8][4];                 // [m][n-pair], packed f32x2
    #pragma unroll
    for (int m = 0; m < 8; m++)
        #pragma unroll
        for (int p = 0; p < 4; p++) acc2[m][p] = 0ull;

    for (int k0 = 0; k0 < 128; k0 += 16) {
        #pragma unroll
        for (int i = 0; i < 2; i++) {
            int idx = t + i * 256;
            int r = idx >> 2;
            int c4 = idx & 3;
            float4 v = make_float4(0.f, 0.f, 0.f, 0.f);
            if (row0 + r < M)
                v = *(const float4*)&A[(long long)(row0 + r) * 128 + k0 + c4 * 4];
            As[c4 * 4 + 0][r] = v.x;
            As[c4 * 4 + 1][r] = v.y;
            As[c4 * 4 + 2][r] = v.z;
            As[c4 * 4 + 3][r] = v.w;
        }
        #pragma unroll
        for (int i = 0; i < 2; i++) {
            int idx = t + i * 256;
            int r = idx >> 5;
            int c4 = idx & 31;
            *(float4*)&Ws[r][c4 * 4] = *(const float4*)&W[(k0 + r) * 128 + c4 * 4];
        }
        __syncthreads();
        #pragma unroll
        for (int k = 0; k < 16; k++) {
            // B pairs straight from smem (consecutive n are contiguous)
            ulonglong2 b01 = *(const ulonglong2*)&Ws[k][tx * 8];
            ulonglong2 b23 = *(const ulonglong2*)&Ws[k][tx * 8 + 4];
            ull bp[4] = {b01.x, b01.y, b23.x, b23.y};
            float4 a0 = *(const float4*)&As[k][ty * 8];
            float4 a1 = *(const float4*)&As[k][ty * 8 + 4];
            float av[8] = {a0.x, a0.y, a0.z, a0.w, a1.x, a1.y, a1.z, a1.w};
            #pragma unroll
            for (int m = 0; m < 8; m++) {
                ull am = f32x2_bcast(av[m]);
                #pragma unroll
                for (int p = 0; p < 4; p++)
                    acc2[m][p] = f32x2_fma(am, bp[p], acc2[m][p]);
            }
        }
        __syncthreads();
    }

    // unpack accumulators
    float acc[8][8];
    #pragma unroll
    for (int m = 0; m < 8; m++)
        #pragma unroll
        for (int p = 0; p < 4; p++) {
            float2 v = f32x2_unpack(acc2[m][p]);
            acc[m][2 * p] = v.x;
            acc[m][2 * p + 1] = v.y;
        }

    // epilogue: attention logits + h write
    float avs[8], avd[8];
    #pragma unroll
    for (int n = 0; n < 8; n++) {
        avs[n] = att_src[tx * 8 + n];
        avd[n] = att_dst[tx * 8 + n];
    }
    #pragma unroll
    for (int m = 0; m < 8; m++) {
        int r = row0 + ty * 8 + m;
        float ps = 0.f, pd = 0.f;
        #pragma unroll
        for (int n = 0; n < 8; n++) {
            ps += acc[m][n] * avs[n];
            pd += acc[m][n] * avd[n];
        }
        if (HEADS == 4) {
            #pragma unroll
            for (int off = 1; off <= 2; off <<= 1) {
                ps += __shfl_xor_sync(0xffffffffu, ps, off);
                pd += __shfl_xor_sync(0xffffffffu, pd, off);
            }
            if ((tx & 3) == 0 && r < M) {
                g_asrc1[r * 4 + (tx >> 2)] = ps;
                g_adst1[r * 4 + (tx >> 2)] = pd;
            }
        } else {
            #pragma unroll
            for (int off = 1; off <= 8; off <<= 1) {
                ps += __shfl_xor_sync(0xffffffffu, ps, off);
                pd += __shfl_xor_sync(0xffffffffu, pd, off);
            }
            if (tx == 0 && r < M) {
                g_asrc2[r] = ps;
                g_adst2[r] = pd;
            }
        }
        if (r < M) {
            *(float4*)&H[(long long)r * 128 + tx * 8] =
                make_float4(acc[m][0], acc[m][1], acc[m][2], acc[m][3]);
            *(float4*)&H[(long long)r * 128 + tx * 8 + 4] =
                make_float4(acc[m][4], acc[m][5], acc[m][6], acc[m][7]);
        }
    }
}

// ------------------- fused edge softmax + aggregation ----------------------
__device__ __forceinline__ float leaky_exp(float l) {
    l = l > 0.f ? l : NEG_SLOPE * l;
    return __expf(l);
}
__device__ __forceinline__ float elu(float v) {
    return v > 0.f ? v : expm1f(v);
}

// Layer 1: warp per dst node (identical to R3).
__global__ void agg1_kernel(int N, const float* __restrict__ b1) {
    int node = (blockIdx.x * blockDim.x + threadIdx.x) >> 5;
    int lane = threadIdx.x & 31;
    if (node >= N) return;
    int beg = g_off[node], end = g_off[node + 1];
    float4 ad = *(const float4*)&g_adst1[node * 4];
    float acc0 = 0.f, acc1 = 0.f, acc2 = 0.f, acc3 = 0.f;
    float s0 = 0.f, s1 = 0.f, s2 = 0.f, s3 = 0.f;
    for (int base = beg; base < end; base += 32) {
        int e = base + lane;
        int src = 0;
        float w0 = 0.f, w1 = 0.f, w2 = 0.f, w3 = 0.f;
        if (e < end) {
            src = g_srcs[e];
            float4 as = *(const float4*)&g_asrc1[src * 4];
            w0 = leaky_exp(as.x + ad.x);
            w1 = leaky_exp(as.y + ad.y);
            w2 = leaky_exp(as.z + ad.z);
            w3 = leaky_exp(as.w + ad.w);
            s0 += w0; s1 += w1; s2 += w2; s3 += w3;
        }
        int cnt = min(32, end - base);
        #pragma unroll 4
        for (int j = 0; j < cnt; j++) {
            int   sj = __shfl_sync(0xffffffffu, src, j);
            float u0 = __shfl_sync(0xffffffffu, w0, j);
            float u1 = __shfl_sync(0xffffffffu, w1, j);
            float u2 = __shfl_sync(0xffffffffu, w2, j);
            float u3 = __shfl_sync(0xffffffffu, w3, j);
            const float* hp = &g_h1[(long long)sj * 128];
            acc0 += u0 * hp[lane];
            acc1 += u1 * hp[32 + lane];
            acc2 += u2 * hp[64 + lane];
            acc3 += u3 * hp[96 + lane];
        }
    }
    #pragma unroll
    for (int off = 16; off; off >>= 1) {
        s0 += __shfl_xor_sync(0xffffffffu, s0, off);
        s1 += __shfl_xor_sync(0xffffffffu, s1, off);
        s2 += __shfl_xor_sync(0xffffffffu, s2, off);
        s3 += __shfl_xor_sync(0xffffffffu, s3, off);
    }
    float* op = &g_act1[(long long)node * 128];
    float o;
    o = acc0 / (s0 + 1e-16f) + b1[lane];       op[lane]      = elu(o);
    o = acc1 / (s1 + 1e-16f) + b1[32 + lane];  op[32 + lane] = elu(o);
    o = acc2 / (s2 + 1e-16f) + b1[64 + lane];  op[64 + lane] = elu(o);
    o = acc3 / (s3 + 1e-16f) + b1[96 + lane];  op[96 + lane] = elu(o);
}

// Layer 2: single head (identical to R3). -> d_out
__global__ void agg2_kernel(int N, const float* __restrict__ b2,
                            float* __restrict__ out) {
    int node = (blockIdx.x * blockDim.x + threadIdx.x) >> 5;
    int lane = threadIdx.x & 31;
    if (node >= N) return;
    int beg = g_off[node], end = g_off[node + 1];
    float ad = g_adst2[node];
    float acc0 = 0.f, acc1 = 0.f, acc2 = 0.f, acc3 = 0.f, s = 0.f;
    for (int base = beg; base < end; base += 32) {
        int e = base + lane;
        int src = 0;
        float w = 0.f;
        if (e < end) {
            src = g_srcs[e];
            w = leaky_exp(g_asrc2[src] + ad);
            s += w;
        }
        int cnt = min(32, end - base);
        #pragma unroll 4
        for (int j = 0; j < cnt; j++) {
            int   sj = __shfl_sync(0xffffffffu, src, j);
            float u  = __shfl_sync(0xffffffffu, w, j);
            const float* hp = &g_h2[(long long)sj * 128];
            acc0 += u * hp[lane];
            acc1 += u * hp[32 + lane];
            acc2 += u * hp[64 + lane];
            acc3 += u * hp[96 + lane];
        }
    }
    #pragma unroll
    for (int off = 16; off; off >>= 1)
        s += __shfl_xor_sync(0xffffffffu, s, off);
    float inv = 1.f / (s + 1e-16f);
    float* op = &out[(long long)node * 128];
    float o;
    o = acc0 * inv + b2[lane];       op[lane]      = elu(o);
    o = acc1 * inv + b2[32 + lane];  op[32 + lane] = elu(o);
    o = acc2 * inv + b2[64 + lane];  op[64 + lane] = elu(o);
    o = acc3 * inv + b2[96 + lane];  op[96 + lane] = elu(o);
}

// ------------------------------- launch ------------------------------------
extern "C" void kernel_launch(void* const* d_in, const int* in_sizes, int n_in,
                              void* d_out, int out_size) {
    const float* x        = (const float*)d_in[0];
    const void*  a        = d_in[1];
    const float* W1       = (const float*)d_in[2];
    const float* att_src1 = (const float*)d_in[3];
    const float* att_dst1 = (const float*)d_in[4];
    const float* b1       = (const float*)d_in[5];
    const float* W2       = (const float*)d_in[6];
    const float* att_src2 = (const float*)d_in[7];
    const float* att_dst2 = (const float*)d_in[8];
    const float* b2       = (const float*)d_in[9];
    float* out = (float*)d_out;

    void *p_h1 = 0, *p_act1 = 0, *p_h2 = 0;
    cudaGetSymbolAddress(&p_h1, g_h1);
    cudaGetSymbolAddress(&p_act1, g_act1);
    cudaGetSymbolAddress(&p_h2, g_h2);
    float* h1   = (float*)p_h1;
    float* act1 = (float*)p_act1;
    float* h2   = (float*)p_h2;

    int N = in_sizes[0] / 128;
    int E = in_sizes[1] / 2;

    int eg = (E + 255) / 256;
    int ng = (N + 255) / 256;
    int wg = (N + 7) / 8;
    int gg = (N + 127) / 128;
    int sb = (N + SCAN_CHUNK - 1) / SCAN_CHUNK;

    detect_kernel<<<1, 32>>>(a, N);
    zero_cnt_kernel<<<ng, 256>>>(N);
    hist_kernel<<<eg, 256>>>(a, E);
    scanA_kernel<<<sb, 1024>>>(N);
    scanB_kernel<<<1, 32>>>(sb, N);
    scanC_kernel<<<ng, 256>>>(N);
    scatter_kernel<<<eg, 256>>>(a, E);

    // Layer 1
    gemm_att_kernel<4><<<gg, 256>>>(x, W1, att_src1, att_dst1, h1, N);
    agg1_kernel<<<wg, 256>>>(N, b1);

    // Layer 2
    gemm_att_kernel<1><<<gg, 256>>>(act1, W2, att_src2, att_dst2, h2, N);
    agg2_kernel<<<wg, 256>>>(N, b2, out);
}

// round 8
// speedup vs baseline: 1.2765x; 1.0663x over previous
#include <cuda_runtime.h>
#include <cuda_fp16.h>
#include <math.h>

// ---------------------------------------------------------------------------
// GAT graph encoder, 2 layers. CSR-by-dst per call; softmax max cancels.
// R5 + : fp16 h storage (wide 8B/lane agg gathers), hist fused into GEMM1
// grid, parallel edge-dtype detect. Logits/accum all fp32.
// ---------------------------------------------------------------------------

#define NMAX 100000
#define EMAX 1600000
#define NEG_SLOPE 0.2f
#define SCAN_CHUNK 4096

typedef unsigned long long ull;

__device__ __half g_h1h[NMAX * 128];   // layer1 features fp16
__device__ __half g_h2h[NMAX * 128];   // layer2 features fp16
__device__ float  g_act1[NMAX * 128];  // layer1 activations (GEMM2 input) fp32
__device__ float  g_asrc1[NMAX * 4];
__device__ float  g_adst1[NMAX * 4];
__device__ float  g_asrc2[NMAX];
__device__ float  g_adst2[NMAX];
__device__ int    g_cnt[NMAX];
__device__ int    g_off[NMAX + 1];
__device__ int    g_pos[NMAX];
__device__ int    g_srcs[EMAX];
__device__ int    g_bsum[64];
__device__ int    g_bpre[64];
__device__ int    g_is64;

// ------------------------- packed fp32 helpers -----------------------------
__device__ __forceinline__ ull f32x2_bcast(float a) {
    ull d;
    asm("mov.b64 %0, {%1, %1};" : "=l"(d) : "f"(a));
    return d;
}
__device__ __forceinline__ ull f32x2_fma(ull a, ull b, ull c) {
    ull d;
    asm("fma.rn.f32x2 %0, %1, %2, %3;" : "=l"(d) : "l"(a), "l"(b), "l"(c));
    return d;
}
__device__ __forceinline__ float2 f32x2_unpack(ull p) {
    float2 r;
    asm("mov.b64 {%0, %1}, %2;" : "=f"(r.x), "=f"(r.y) : "l"(p));
    return r;
}

// --------------------------- edge dtype sniffing ---------------------------
// Parallel: 256 threads each test one u64 word; any >= N  =>  data is int32.
__global__ void detect_kernel(const void* a, int n_nodes) {
    __shared__ int s_bad;
    int i = threadIdx.x;
    if (i == 0) s_bad = 0;
    __syncthreads();
    const ull* p = (const ull*)a;
    if (p[i] >= (ull)n_nodes) atomicAdd(&s_bad, 1);
    __syncthreads();
    if (i == 0) g_is64 = (s_bad == 0) ? 1 : 0;
}

__device__ __forceinline__ int edge_val(const void* a, long long idx) {
    if (g_is64) return (int)((const long long*)a)[idx];
    return ((const int*)a)[idx];
}

// ------------------------------- CSR build ---------------------------------
__global__ void zero_cnt_kernel(int n) {
    int i = blockIdx.x * blockDim.x + threadIdx.x;
    if (i < n) g_cnt[i] = 0;
}

__global__ void scanA_kernel(int n) {
    __shared__ int wsum[32];
    int b = blockIdx.x, tid = threadIdx.x;
    int lane = tid & 31, warp = tid >> 5;
    int base = b * SCAN_CHUNK + tid * 4;
    int v0 = 0, v1 = 0, v2 = 0, v3 = 0;
    if (base + 3 < n) {
        int4 v = *(const int4*)&g_cnt[base];
        v0 = v.x; v1 = v.y; v2 = v.z; v3 = v.w;
    } else if (base < n) {
        v0 = g_cnt[base];
        if (base + 1 < n) v1 = g_cnt[base + 1];
        if (base + 2 < n) v2 = g_cnt[base + 2];
    }
    int tsum = v0 + v1 + v2 + v3;
    int x = tsum;
    #pragma unroll
    for (int d = 1; d < 32; d <<= 1) {
        int t = __shfl_up_sync(0xffffffffu, x, d);
        if (lane >= d) x += t;
    }
    if (lane == 31) wsum[warp] = x;
    __syncthreads();
    if (warp == 0) {
        int y = wsum[lane];
        #pragma unroll
        for (int d = 1; d < 32; d <<= 1) {
            int t = __shfl_up_sync(0xffffffffu, y, d);
            if (lane >= d) y += t;
        }
        wsum[lane] = y;
    }
    __syncthreads();
    int excl = (warp ? wsum[warp - 1] : 0) + (x - tsum);
    if (base < n) {
        g_off[base] = excl;
        if (base + 1 < n) g_off[base + 1] = excl + v0;
        if (base + 2 < n) g_off[base + 2] = excl + v0 + v1;
        if (base + 3 < n) g_off[base + 3] = excl + v0 + v1 + v2;
    }
    if (tid == 0) g_bsum[b] = wsum[31];
}

__global__ void scanB_kernel(int nblocks, int n) {
    int lane = threadIdx.x;
    int v = (lane < nblocks) ? g_bsum[lane] : 0;
    int x = v;
    #pragma unroll
    for (int d = 1; d < 32; d <<= 1) {
        int t = __shfl_up_sync(0xffffffffu, x, d);
        if (lane >= d) x += t;
    }
    if (lane < nblocks) g_bpre[lane] = x - v;
    if (lane == 31) g_off[n] = x;
}

__global__ void scanC_kernel(int n) {
    int i = blockIdx.x * blockDim.x + threadIdx.x;
    if (i < n) {
        int o = g_off[i] + g_bpre[i >> 12];
        g_off[i] = o;
        g_pos[i] = o;
    }
}

__global__ void scatter_kernel(const void* a, int E) {
    int e = blockIdx.x * blockDim.x + threadIdx.x;
    if (e >= E) return;
    int src = edge_val(a, e);
    int dst = edge_val(a, (long long)E + e);
    int p = atomicAdd(&g_pos[dst], 1);
    g_srcs[p] = src;
}

// --------------- GEMM (f32x2) + attention epilogue (+hist) -----------------
// C[M,128] = A[M,128] @ W[128,128], fp32 via packed fma.rn.f32x2.
// Writes h (fp16) + per-node attention logits (fp32). Blocks beyond
// gemm_blocks instead run the destination histogram (layer1 only).
template <int HEADS>
__global__ void gemm_att_kernel(const float* __restrict__ A,
                                const float* __restrict__ W,
                                const float* __restrict__ att_src,
                                const float* __restrict__ att_dst,
                                __half* __restrict__ H, int M,
                                int gemm_blocks, const void* ea, int E) {
    __shared__ float As[16][132];   // transposed A tile
    __shared__ float Ws[16][128];

    if (blockIdx.x >= gemm_blocks) {        // histogram side-work
        int e = (blockIdx.x - gemm_blocks) * blockDim.x + threadIdx.x;
        if (e < E) {
            int dst = edge_val(ea, (long long)E + e);
            atomicAdd(&g_cnt[dst], 1);
        }
        return;
    }

    int t = threadIdx.x;
    int tx = t & 15;
    int ty = t >> 4;
    int row0 = blockIdx.x * 128;
    ull acc2[8][4];
    #pragma unroll
    for (int m = 0; m < 8; m++)
        #pragma unroll
        for (int p = 0; p < 4; p++) acc2[m][p] = 0ull;

    for (int k0 = 0; k0 < 128; k0 += 16) {
        #pragma unroll
        for (int i = 0; i < 2; i++) {
            int idx = t + i * 256;
            int r = idx >> 2;
            int c4 = idx & 3;
            float4 v = make_float4(0.f, 0.f, 0.f, 0.f);
            if (row0 + r < M)
                v = *(const float4*)&A[(long long)(row0 + r) * 128 + k0 + c4 * 4];
            As[c4 * 4 + 0][r] = v.x;
            As[c4 * 4 + 1][r] = v.y;
            As[c4 * 4 + 2][r] = v.z;
            As[c4 * 4 + 3][r] = v.w;
        }
        #pragma unroll
        for (int i = 0; i < 2; i++) {
            int idx = t + i * 256;
            int r = idx >> 5;
            int c4 = idx & 31;
            *(float4*)&Ws[r][c4 * 4] = *(const float4*)&W[(k0 + r) * 128 + c4 * 4];
        }
        __syncthreads();
        #pragma unroll
        for (int k = 0; k < 16; k++) {
            ulonglong2 b01 = *(const ulonglong2*)&Ws[k][tx * 8];
            ulonglong2 b23 = *(const ulonglong2*)&Ws[k][tx * 8 + 4];
            ull bp[4] = {b01.x, b01.y, b23.x, b23.y};
            float4 a0 = *(const float4*)&As[k][ty * 8];
            float4 a1 = *(const float4*)&As[k][ty * 8 + 4];
            float av[8] = {a0.x, a0.y, a0.z, a0.w, a1.x, a1.y, a1.z, a1.w};
            #pragma unroll
            for (int m = 0; m < 8; m++) {
                ull am = f32x2_bcast(av[m]);
                #pragma unroll
                for (int p = 0; p < 4; p++)
                    acc2[m][p] = f32x2_fma(am, bp[p], acc2[m][p]);
            }
        }
        __syncthreads();
    }

    float acc[8][8];
    #pragma unroll
    for (int m = 0; m < 8; m++)
        #pragma unroll
        for (int p = 0; p < 4; p++) {
            float2 v = f32x2_unpack(acc2[m][p]);
            acc[m][2 * p] = v.x;
            acc[m][2 * p + 1] = v.y;
        }

    float avs[8], avd[8];
    #pragma unroll
    for (int n = 0; n < 8; n++) {
        avs[n] = att_src[tx * 8 + n];
        avd[n] = att_dst[tx * 8 + n];
    }
    #pragma unroll
    for (int m = 0; m < 8; m++) {
        int r = row0 + ty * 8 + m;
        float ps = 0.f, pd = 0.f;
        #pragma unroll
        for (int n = 0; n < 8; n++) {
            ps += acc[m][n] * avs[n];
            pd += acc[m][n] * avd[n];
        }
        if (HEADS == 4) {
            #pragma unroll
            for (int off = 1; off <= 2; off <<= 1) {
                ps += __shfl_xor_sync(0xffffffffu, ps, off);
                pd += __shfl_xor_sync(0xffffffffu, pd, off);
            }
            if ((tx & 3) == 0 && r < M) {
                g_asrc1[r * 4 + (tx >> 2)] = ps;
                g_adst1[r * 4 + (tx >> 2)] = pd;
            }
        } else {
            #pragma unroll
            for (int off = 1; off <= 8; off <<= 1) {
                ps += __shfl_xor_sync(0xffffffffu, ps, off);
                pd += __shfl_xor_sync(0xffffffffu, pd, off);
            }
            if (tx == 0 && r < M) {
                g_asrc2[r] = ps;
                g_adst2[r] = pd;
            }
        }
        if (r < M) {
            __half hh[8];
            #pragma unroll
            for (int q = 0; q < 8; q++) hh[q] = __float2half_rn(acc[m][q]);
            *(uint4*)&H[(long long)r * 128 + tx * 8] = *(uint4*)hh;
        }
    }
}

// ------------------- fused edge softmax + aggregation ----------------------
__device__ __forceinline__ float leaky_exp(float l) {
    l = l > 0.f ? l : NEG_SLOPE * l;
    return __expf(l);
}
__device__ __forceinline__ float elu(float v) {
    return v > 0.f ? v : expm1f(v);
}

// Layer 1: one warp per dst node. Lane covers channels 4l..4l+3 (head l>>3);
// gather is one 8B load per lane per edge (256B/warp = full fp16 row).
__global__ void agg1_kernel(int N, const float* __restrict__ b1) {
    int node = (blockIdx.x * blockDim.x + threadIdx.x) >> 5;
    int lane = threadIdx.x & 31;
    if (node >= N) return;
    int beg = g_off[node], end = g_off[node + 1];
    float4 ad = *(const float4*)&g_adst1[node * 4];
    int head = lane >> 3;
    float a0 = 0.f, a1 = 0.f, a2 = 0.f, a3 = 0.f;   // 4 channels of this lane
    float s0 = 0.f, s1 = 0.f, s2 = 0.f, s3 = 0.f;
    for (int base = beg; base < end; base += 32) {
        int e = base + lane;
        int src = 0;
        float w0 = 0.f, w1 = 0.f, w2 = 0.f, w3 = 0.f;
        if (e < end) {
            src = g_srcs[e];
            float4 as = *(const float4*)&g_asrc1[src * 4];
            w0 = leaky_exp(as.x + ad.x);
            w1 = leaky_exp(as.y + ad.y);
            w2 = leaky_exp(as.z + ad.z);
            w3 = leaky_exp(as.w + ad.w);
            s0 += w0; s1 += w1; s2 += w2; s3 += w3;
        }
        int cnt = min(32, end - base);
        #pragma unroll 4
        for (int j = 0; j < cnt; j++) {
            int   sj = __shfl_sync(0xffffffffu, src, j);
            float u0 = __shfl_sync(0xffffffffu, w0, j);
            float u1 = __shfl_sync(0xffffffffu, w1, j);
            float u2 = __shfl_sync(0xffffffffu, w2, j);
            float u3 = __shfl_sync(0xffffffffu, w3, j);
            float uw = (head == 0) ? u0 : (head == 1) ? u1 : (head == 2) ? u2 : u3;
            uint2 hv = *(const uint2*)&g_h1h[(long long)sj * 128 + 4 * lane];
            float2 f0 = __half22float2(*(__half2*)&hv.x);
            float2 f1 = __half22float2(*(__half2*)&hv.y);
            a0 += uw * f0.x; a1 += uw * f0.y;
            a2 += uw * f1.x; a3 += uw * f1.y;
        }
    }
    #pragma unroll
    for (int off = 16; off; off >>= 1) {
        s0 += __shfl_xor_sync(0xffffffffu, s0, off);
        s1 += __shfl_xor_sync(0xffffffffu, s1, off);
        s2 += __shfl_xor_sync(0xffffffffu, s2, off);
        s3 += __shfl_xor_sync(0xffffffffu, s3, off);
    }
    float sw = (head == 0) ? s0 : (head == 1) ? s1 : (head == 2) ? s2 : s3;
    float inv = 1.f / (sw + 1e-16f);
    int c0 = 4 * lane;
    float4 bv = *(const float4*)&b1[c0];
    float4 o;
    o.x = elu(a0 * inv + bv.x);
    o.y = elu(a1 * inv + bv.y);
    o.z = elu(a2 * inv + bv.z);
    o.w = elu(a3 * inv + bv.w);
    *(float4*)&g_act1[(long long)node * 128 + c0] = o;
}

// Layer 2: single head; same wide-gather structure. -> d_out (fp32)
__global__ void agg2_kernel(int N, const float* __restrict__ b2,
                            float* __restrict__ out) {
    int node = (blockIdx.x * blockDim.x + threadIdx.x) >> 5;
    int lane = threadIdx.x & 31;
    if (node >= N) return;
    int beg = g_off[node], end = g_off[node + 1];
    float ad = g_adst2[node];
    float a0 = 0.f, a1 = 0.f, a2 = 0.f, a3 = 0.f, s = 0.f;
    for (int base = beg; base < end; base += 32) {
        int e = base + lane;
        int src = 0;
        float w = 0.f;
        if (e < end) {
            src = g_srcs[e];
            w = leaky_exp(g_asrc2[src] + ad);
            s += w;
        }
        int cnt = min(32, end - base);
        #pragma unroll 4
        for (int j = 0; j < cnt; j++) {
            int   sj = __shfl_sync(0xffffffffu, src, j);
            float u  = __shfl_sync(0xffffffffu, w, j);
            uint2 hv = *(const uint2*)&g_h2h[(long long)sj * 128 + 4 * lane];
            float2 f0 = __half22float2(*(__half2*)&hv.x);
            float2 f1 = __half22float2(*(__half2*)&hv.y);
            a0 += u * f0.x; a1 += u * f0.y;
            a2 += u * f1.x; a3 += u * f1.y;
        }
    }
    #pragma unroll
    for (int off = 16; off; off >>= 1)
        s += __shfl_xor_sync(0xffffffffu, s, off);
    float inv = 1.f / (s + 1e-16f);
    int c0 = 4 * lane;
    float4 bv = *(const float4*)&b2[c0];
    float4 o;
    o.x = elu(a0 * inv + bv.x);
    o.y = elu(a1 * inv + bv.y);
    o.z = elu(a2 * inv + bv.z);
    o.w = elu(a3 * inv + bv.w);
    *(float4*)&out[(long long)node * 128 + c0] = o;
}

// ------------------------------- launch ------------------------------------
extern "C" void kernel_launch(void* const* d_in, const int* in_sizes, int n_in,
                              void* d_out, int out_size) {
    const float* x        = (const float*)d_in[0];
    const void*  a        = d_in[1];
    const float* W1       = (const float*)d_in[2];
    const float* att_src1 = (const float*)d_in[3];
    const float* att_dst1 = (const float*)d_in[4];
    const float* b1       = (const float*)d_in[5];
    const float* W2       = (const float*)d_in[6];
    const float* att_src2 = (const float*)d_in[7];
    const float* att_dst2 = (const float*)d_in[8];
    const float* b2       = (const float*)d_in[9];
    float* out = (float*)d_out;

    void *p_h1 = 0, *p_act1 = 0, *p_h2 = 0;
    cudaGetSymbolAddress(&p_h1, g_h1h);
    cudaGetSymbolAddress(&p_act1, g_act1);
    cudaGetSymbolAddress(&p_h2, g_h2h);
    __half* h1  = (__half*)p_h1;
    float* act1 = (float*)p_act1;
    __half* h2  = (__half*)p_h2;

    int N = in_sizes[0] / 128;
    int E = in_sizes[1] / 2;

    int eg = (E + 255) / 256;
    int ng = (N + 255) / 256;
    int wg = (N + 7) / 8;
    int gg = (N + 127) / 128;
    int sb = (N + SCAN_CHUNK - 1) / SCAN_CHUNK;

    detect_kernel<<<1, 256>>>(a, N);
    zero_cnt_kernel<<<ng, 256>>>(N);

    // Layer 1 GEMM with fused destination histogram in trailing blocks
    gemm_att_kernel<4><<<gg + eg, 256>>>(x, W1, att_src1, att_dst1, h1, N,
                                         gg, a, E);
    scanA_kernel<<<sb, 1024>>>(N);
    scanB_kernel<<<1, 32>>>(sb, N);
    scanC_kernel<<<ng, 256>>>(N);
    scatter_kernel<<<eg, 256>>>(a, E);

    agg1_kernel<<<wg, 256>>>(N, b1);

    // Layer 2
    gemm_att_kernel<1><<<gg, 256>>>(act1, W2, att_src2, att_dst2, h2, N,
                                    gg, (const void*)0, 0);
    agg2_kernel<<<wg, 256>>>(N, b2, out);
}